// round 15
// baseline (speedup 1.0000x reference)
#include <cuda_runtime.h>
#include <cuda_fp16.h>
#include <math.h>

#define NMAX 100000
#define EMAX 3200000
#define IN_F 128
#define HID 64
#define CAT 192
#define OUT_F 40
#define LN_EPS 1e-5f
#define NBMAX 128

// ---------------- device scratch ----------------
__device__ int     g_deg[NMAX];          // in-degree WITHOUT self loop
__device__ int     g_rowptr[NMAX + 1];   // padded rowptr (deg rounded up to mult of 8)
__device__ int     g_cursor[NMAX];
__device__ int     g_csrc[EMAX + 8 * NMAX];
__device__ int     g_bsum[NBMAX];
__device__ int     g_boff[NBMAX];
__device__ float   g_dis[NMAX];          // (deg+1)^-1/2
__device__ float   g_sdeg[NMAX];         // (deg+1)^+1/2
__device__ float   g_invdeg[NMAX];       // 1/(deg+1)
// row NMAX is the zero pad row: never written, zero-initialized at module load
__device__ __align__(16) __half2 g_uA[(NMAX + 1) * 32];
__device__ __align__(16) __half2 g_uB[(NMAX + 1) * 32];
__device__ __align__(16) __half2 g_hcat2[NMAX * 96];

__device__ __forceinline__ float gelu_exact(float x) {
    return 0.5f * x * (1.0f + erff(x * 0.70710678118654752f));
}

// ---------------- preprocessing ----------------
__global__ void k_hist(const int* __restrict__ ei, int e) {
    int i = blockIdx.x * blockDim.x + threadIdx.x;
    if (i < e) atomicAdd(&g_deg[ei[e + i]], 1);
}

// per-1024-block sums of PADDED degree, fused with aux (dis/sdeg/invdeg)
__global__ void __launch_bounds__(1024) k_blocksum(int n) {
    __shared__ int ws[32];
    int tid = threadIdx.x, lane = tid & 31, wid = tid >> 5;
    int idx = blockIdx.x * 1024 + tid;
    int v = (idx < n) ? g_deg[idx] : 0;
    if (idx < n) {
        float d = (float)(v + 1);
        g_dis[idx] = rsqrtf(d);
        g_sdeg[idx] = sqrtf(d);
        g_invdeg[idx] = 1.0f / d;
    }
    int pv = (idx < n) ? ((v + 7) & ~7) : 0;   // padded degree
    int s = pv;
    #pragma unroll
    for (int o = 16; o; o >>= 1) s += __shfl_xor_sync(0xffffffffu, s, o);
    if (lane == 0) ws[wid] = s;
    __syncthreads();
    if (wid == 0) {
        int u = ws[lane];
        #pragma unroll
        for (int o = 16; o; o >>= 1) u += __shfl_xor_sync(0xffffffffu, u, o);
        if (lane == 0) g_bsum[blockIdx.x] = u;
    }
}

// scans block sums AND writes the padded grand total to g_rowptr[n]
__global__ void k_scanbsums(int nb, int n) {
    int lane = threadIdx.x;
    int carry = 0;
    for (int base = 0; base < nb; base += 32) {
        int idx = base + lane;
        int v = (idx < nb) ? g_bsum[idx] : 0;
        int orig = v;
        #pragma unroll
        for (int o = 1; o < 32; o <<= 1) {
            int t = __shfl_up_sync(0xffffffffu, v, o);
            if (lane >= o) v += t;
        }
        if (idx < nb) g_boff[idx] = carry + v - orig;
        carry += __shfl_sync(0xffffffffu, v, 31);
    }
    if (lane == 0) g_rowptr[n] = carry;   // total padded edge count
}

__global__ void __launch_bounds__(1024) k_scanlocal(int n) {
    __shared__ int wsum[32], woff[32];
    int tid = threadIdx.x, lane = tid & 31, wid = tid >> 5;
    int idx = blockIdx.x * 1024 + tid;
    int pv = (idx < n) ? ((g_deg[idx] + 7) & ~7) : 0;
    int v = pv;
    #pragma unroll
    for (int o = 1; o < 32; o <<= 1) {
        int t = __shfl_up_sync(0xffffffffu, v, o);
        if (lane >= o) v += t;
    }
    if (lane == 31) wsum[wid] = v;
    __syncthreads();
    if (wid == 0) {
        int u = wsum[lane];
        int s = u;
        #pragma unroll
        for (int o = 1; o < 32; o <<= 1) {
            int t = __shfl_up_sync(0xffffffffu, s, o);
            if (lane >= o) s += t;
        }
        woff[lane] = s - u;
    }
    __syncthreads();
    int excl = (v - pv) + woff[wid] + g_boff[blockIdx.x];
    if (idx < n) { g_rowptr[idx] = excl; g_cursor[idx] = excl; }
}

// fill pad slots [rowptr+deg, rowptr+pdeg) with the zero row index n
__global__ void k_fillpad(int n) {
    int i = blockIdx.x * blockDim.x + threadIdx.x;
    if (i < n) {
        int d = g_deg[i];
        int start = g_rowptr[i] + d;
        int stop  = g_rowptr[i] + ((d + 7) & ~7);
        for (int t = start; t < stop; t++) g_csrc[t] = n;
    }
}

__global__ void k_scatter(const int* __restrict__ ei, int e) {
    int i = blockIdx.x * blockDim.x + threadIdx.x;
    if (i < e) {
        int s = ei[i], d = ei[e + i];
        int pos = atomicAdd(&g_cursor[d], 1);
        g_csrc[pos] = s;
    }
}

// ---------------- layer1 GEMM + gelu + LN(64) + dis -> fp16 u0 ----------------
__global__ void __launch_bounds__(256) k_gemm1(const float* __restrict__ x,
                                               const float* __restrict__ W1,
                                               const float* __restrict__ b1,
                                               const float* __restrict__ g1,
                                               const float* __restrict__ be1, int n) {
    __shared__ float xs[64][65];
    __shared__ float ws[64 * 64];
    int tid = threadIdx.x;
    int node0 = blockIdx.x * 64;
    int r = tid >> 2, q = tid & 3;
    float acc[16];
    #pragma unroll
    for (int j = 0; j < 16; j++) acc[j] = 0.f;
    for (int kc = 0; kc < 2; kc++) {
        __syncthreads();
        for (int i = tid; i < 4096; i += 256) ws[i] = W1[kc * 4096 + i];
        for (int i = tid; i < 4096; i += 256) {
            int rr = i >> 6, cc = i & 63;
            int gn = node0 + rr;
            xs[rr][cc] = (gn < n) ? x[gn * IN_F + kc * 64 + cc] : 0.f;
        }
        __syncthreads();
        #pragma unroll 8
        for (int k = 0; k < 64; k++) {
            float xv = xs[r][k];
            const float* wrow = &ws[k * 64];
            #pragma unroll
            for (int j = 0; j < 16; j++) acc[j] = fmaf(xv, wrow[q + 4 * j], acc[j]);
        }
    }
    int gn = node0 + r;
    float s = 0.f, ss = 0.f;
    #pragma unroll
    for (int j = 0; j < 16; j++) {
        int c = q + 4 * j;
        float t = gelu_exact(acc[j] + b1[c]);
        acc[j] = t;
        s += t; ss += t * t;
    }
    s += __shfl_xor_sync(0xffffffffu, s, 1);
    s += __shfl_xor_sync(0xffffffffu, s, 2);
    ss += __shfl_xor_sync(0xffffffffu, ss, 1);
    ss += __shfl_xor_sync(0xffffffffu, ss, 2);
    float mu = s * (1.f / 64.f);
    float var = ss * (1.f / 64.f) - mu * mu;
    float rst = rsqrtf(var + LN_EPS);
    float dis = (gn < n) ? g_dis[gn] : 0.f;
    __syncthreads();
    #pragma unroll
    for (int j = 0; j < 16; j++) {
        int c = q + 4 * j;
        xs[r][c] = ((acc[j] - mu) * rst * g1[c] + be1[c]) * dis;
    }
    __syncthreads();
    for (int i = tid; i < 64 * 32; i += 256) {
        int rr = i >> 5, hc = i & 31;
        int g = node0 + rr;
        if (g < n) g_uA[g * 32 + hc] = __floats2half2_rn(xs[rr][2 * hc], xs[rr][2 * hc + 1]);
    }
}

// ---------------- SpMM hop: 8-lane groups, branch-free padded unroll-8 ----------------
__device__ __forceinline__ void acc_f4(float2 a[4], float4 v) {
    a[0].x += __low2float(*reinterpret_cast<__half2*>(&v.x));
    a[0].y += __high2float(*reinterpret_cast<__half2*>(&v.x));
    a[1].x += __low2float(*reinterpret_cast<__half2*>(&v.y));
    a[1].y += __high2float(*reinterpret_cast<__half2*>(&v.y));
    a[2].x += __low2float(*reinterpret_cast<__half2*>(&v.z));
    a[2].y += __high2float(*reinterpret_cast<__half2*>(&v.z));
    a[3].x += __low2float(*reinterpret_cast<__half2*>(&v.w));
    a[3].y += __high2float(*reinterpret_cast<__half2*>(&v.w));
}

__global__ void __launch_bounds__(256) k_spmm(int dir, int n) {
    int row = (blockIdx.x * blockDim.x + threadIdx.x) >> 3;  // 8-lane group per row
    int gl = threadIdx.x & 7;
    if (row >= n) return;
    const float4* __restrict__ hin = dir ? (const float4*)g_uB : (const float4*)g_uA;
    float4* __restrict__ hout      = dir ? (float4*)g_uA : (float4*)g_uB;
    int beg = __ldg(&g_rowptr[row]), end = __ldg(&g_rowptr[row + 1]);
    int len = end - beg;   // multiple of 8
    const int* __restrict__ cs = g_csrc + beg;
    float2 acc[4] = {{0.f,0.f},{0.f,0.f},{0.f,0.f},{0.f,0.f}};
    // self loop
    acc_f4(acc, __ldg(&hin[row * 8 + gl]));
    for (int k = 0; k < len; k += 8) {
        int s0 = __ldg(cs + k + 0);
        int s1 = __ldg(cs + k + 1);
        int s2 = __ldg(cs + k + 2);
        int s3 = __ldg(cs + k + 3);
        int s4 = __ldg(cs + k + 4);
        int s5 = __ldg(cs + k + 5);
        int s6 = __ldg(cs + k + 6);
        int s7 = __ldg(cs + k + 7);
        float4 v0 = __ldg(&hin[s0 * 8 + gl]);
        float4 v1 = __ldg(&hin[s1 * 8 + gl]);
        float4 v2 = __ldg(&hin[s2 * 8 + gl]);
        float4 v3 = __ldg(&hin[s3 * 8 + gl]);
        float4 v4 = __ldg(&hin[s4 * 8 + gl]);
        float4 v5 = __ldg(&hin[s5 * 8 + gl]);
        float4 v6 = __ldg(&hin[s6 * 8 + gl]);
        float4 v7 = __ldg(&hin[s7 * 8 + gl]);
        acc_f4(acc, v0); acc_f4(acc, v1); acc_f4(acc, v2); acc_f4(acc, v3);
        acc_f4(acc, v4); acc_f4(acc, v5); acc_f4(acc, v6); acc_f4(acc, v7);
    }
    float w = __ldg(&g_invdeg[row]);
    float4 o;
    *reinterpret_cast<__half2*>(&o.x) = __floats2half2_rn(acc[0].x * w, acc[0].y * w);
    *reinterpret_cast<__half2*>(&o.y) = __floats2half2_rn(acc[1].x * w, acc[1].y * w);
    *reinterpret_cast<__half2*>(&o.z) = __floats2half2_rn(acc[2].x * w, acc[2].y * w);
    *reinterpret_cast<__half2*>(&o.w) = __floats2half2_rn(acc[3].x * w, acc[3].y * w);
    hout[row * 8 + gl] = o;
}

// ---------------- per-power GEMM -> fp16 hcat (staged through smem) ----------------
__global__ void __launch_bounds__(256) k_mix(int src, const float* __restrict__ Wc,
                                             const float* __restrict__ bc, int off2, int n) {
    __shared__ float xs[64][65];
    __shared__ float ws[64 * 64];
    const __half2* __restrict__ u = src ? g_uB : g_uA;
    int tid = threadIdx.x;
    int node0 = blockIdx.x * 64;
    for (int i = tid; i < 4096; i += 256) ws[i] = Wc[i];
    for (int i = tid; i < 64 * 32; i += 256) {
        int rr = i >> 5, hc = i & 31;
        int gn = node0 + rr;
        float2 v = (gn < n) ? __half22float2(u[gn * 32 + hc]) : make_float2(0.f, 0.f);
        xs[rr][2 * hc] = v.x;
        xs[rr][2 * hc + 1] = v.y;
    }
    __syncthreads();
    int r = tid >> 2, q = tid & 3;
    float acc[16];
    #pragma unroll
    for (int j = 0; j < 16; j++) acc[j] = 0.f;
    #pragma unroll 8
    for (int k = 0; k < 64; k++) {
        float xv = xs[r][k];
        const float* wrow = &ws[k * 64];
        #pragma unroll
        for (int j = 0; j < 16; j++) acc[j] = fmaf(xv, wrow[q + 4 * j], acc[j]);
    }
    int gn = node0 + r;
    float sd = (gn < n) ? g_sdeg[gn] : 0.f;
    __syncthreads();
    #pragma unroll
    for (int j = 0; j < 16; j++) {
        int c = q + 4 * j;
        xs[r][c] = acc[j] * sd + bc[c];
    }
    __syncthreads();
    for (int i = tid; i < 64 * 32; i += 256) {
        int rr = i >> 5, hc = i & 31;
        int g = node0 + rr;
        if (g < n)
            g_hcat2[g * 96 + off2 + hc] = __floats2half2_rn(xs[rr][2 * hc], xs[rr][2 * hc + 1]);
    }
}

// ---------------- final: gelu + LN(192) + GEMM(192x40) ----------------
__global__ void __launch_bounds__(256) k_final(const float* __restrict__ W2,
                                               const float* __restrict__ b2,
                                               const float* __restrict__ g2,
                                               const float* __restrict__ be2,
                                               float* __restrict__ out, int n) {
    __shared__ float w2s[CAT * OUT_F];
    __shared__ float b2s[OUT_F];
    __shared__ float sv[8][CAT];
    int tid = threadIdx.x;
    for (int i = tid; i < CAT * OUT_F; i += 256) w2s[i] = W2[i];
    if (tid < OUT_F) b2s[tid] = b2[tid];
    __syncthreads();
    int wrp = tid >> 5, lane = tid & 31;
    int node = blockIdx.x * 8 + wrp;
    if (node >= n) return;
    float2 v[3];
    float s = 0.f, ss = 0.f;
    #pragma unroll
    for (int jj = 0; jj < 3; jj++) {
        int p = jj * 32 + lane;
        float2 t = __half22float2(g_hcat2[node * 96 + p]);
        t.x = gelu_exact(t.x);
        t.y = gelu_exact(t.y);
        v[jj] = t;
        s += t.x + t.y;
        ss += t.x * t.x + t.y * t.y;
    }
    #pragma unroll
    for (int o = 16; o; o >>= 1) {
        s  += __shfl_xor_sync(0xffffffffu, s, o);
        ss += __shfl_xor_sync(0xffffffffu, ss, o);
    }
    float mu = s * (1.f / 192.f);
    float var = ss * (1.f / 192.f) - mu * mu;
    float r = rsqrtf(var + LN_EPS);
    #pragma unroll
    for (int jj = 0; jj < 3; jj++) {
        int f0 = 2 * (jj * 32 + lane);
        sv[wrp][f0]     = (v[jj].x - mu) * r * g2[f0]     + be2[f0];
        sv[wrp][f0 + 1] = (v[jj].y - mu) * r * g2[f0 + 1] + be2[f0 + 1];
    }
    __syncwarp();
    for (int c = lane; c < OUT_F; c += 32) {
        float a = b2s[c];
        #pragma unroll 8
        for (int k = 0; k < CAT; k++) a = fmaf(sv[wrp][k], w2s[k * OUT_F + c], a);
        out[node * OUT_F + c] = a;
    }
}

// ---------------- host launcher (fork-join concurrency via events) ----------------
extern "C" void kernel_launch(void* const* d_in, const int* in_sizes, int n_in,
                              void* d_out, int out_size) {
    const float* x  = (const float*)d_in[0];
    const int*   ei = (const int*)d_in[1];
    const float* W1 = (const float*)d_in[2];
    const float* b1 = (const float*)d_in[3];
    const float* Wc = (const float*)d_in[4];
    const float* bc = (const float*)d_in[5];
    const float* W2 = (const float*)d_in[6];
    const float* b2 = (const float*)d_in[7];
    const float* g1 = (const float*)d_in[8];
    const float* be1= (const float*)d_in[9];
    const float* g2 = (const float*)d_in[10];
    const float* be2= (const float*)d_in[11];
    float* out = (float*)d_out;

    int n = in_sizes[0] / IN_F;
    int e = in_sizes[1] / 2;
    int nb = (n + 1023) / 1024;

    // side stream + events; created per call, intentionally NOT destroyed
    // (must outlive graph capture/replay; host-side only, no device memory)
    cudaStream_t s2;
    cudaStreamCreateWithFlags(&s2, cudaStreamNonBlocking);
    cudaEvent_t evFork, evPre, evH, evM;
    cudaEventCreateWithFlags(&evFork, cudaEventDisableTiming);
    cudaEventCreateWithFlags(&evPre,  cudaEventDisableTiming);
    cudaEventCreateWithFlags(&evH,    cudaEventDisableTiming);
    cudaEventCreateWithFlags(&evM,    cudaEventDisableTiming);

    void* p = nullptr;
    cudaGetSymbolAddress(&p, g_deg);
    cudaMemsetAsync(p, 0, n * sizeof(int));

    k_hist<<<(e + 255) / 256, 256>>>(ei, e);
    k_blocksum<<<nb, 1024>>>(n);
    k_scanbsums<<<1, 32>>>(nb, n);
    k_scanlocal<<<nb, 1024>>>(n);

    // fork: CSR finalize (fillpad+scatter) on s2, concurrent with gemm1 on main
    cudaEventRecord(evFork, 0);
    cudaStreamWaitEvent(s2, evFork, 0);
    k_gemm1<<<(n + 63) / 64, 256>>>(x, W1, b1, g1, be1, n);   // launch 6 (ncu target)
    k_fillpad<<<(n + 255) / 256, 256, 0, s2>>>(n);
    k_scatter<<<(e + 255) / 256, 256, 0, s2>>>(ei, e);
    cudaEventRecord(evPre, s2);
    cudaStreamWaitEvent(0, evPre, 0);   // hop1 needs csrc

    int sgrid = (n + 31) / 32;
    int wgrid = (n + 7) / 8;
    int mgrid = (n + 63) / 64;
    int dir = 0;
    for (int j = 1; j <= 10; j++) {
        // joins BEFORE the hop that would overwrite the buffer a pending mix reads
        if (j == 8 || j == 10) cudaStreamWaitEvent(0, evM, 0);
        k_spmm<<<sgrid, 256>>>(dir, n);
        int curInB = (dir == 0);
        dir ^= 1;
        if (j == 6) {   // mix6 on s2, overlapped with hop7
            cudaEventRecord(evH, 0);
            cudaStreamWaitEvent(s2, evH, 0);
            k_mix<<<mgrid, 256, 0, s2>>>(curInB, Wc + 6 * HID * HID, bc + 6 * HID, 0, n);
            cudaEventRecord(evM, s2);
        }
        if (j == 8) {   // mix8 on s2, overlapped with hop9
            cudaEventRecord(evH, 0);
            cudaStreamWaitEvent(s2, evH, 0);
            k_mix<<<mgrid, 256, 0, s2>>>(curInB, Wc + 8 * HID * HID, bc + 8 * HID, 32, n);
            cudaEventRecord(evM, s2);
        }
        if (j == 10) {  // mix10 serial on main (final depends on it)
            k_mix<<<mgrid, 256>>>(curInB, Wc + 10 * HID * HID, bc + 10 * HID, 64, n);
        }
    }

    k_final<<<wgrid, 256>>>(W2, b2, g2, be2, out, n);
}

// round 17
// speedup vs baseline: 1.2159x; 1.2159x over previous
#include <cuda_runtime.h>
#include <cuda_fp16.h>
#include <math.h>
#include <stdint.h>

#define NMAX 100000
#define EMAX 3200000
#define IN_F 128
#define HID 64
#define CAT 192
#define OUT_F 40
#define LN_EPS 1e-5f
#define NBMAX 128

// ---------------- device scratch ----------------
__device__ int     g_deg[NMAX];          // in-degree WITHOUT self loop
__device__ int     g_rowptr[NMAX + 1];   // padded rowptr (deg rounded up to mult of 8)
__device__ int     g_cursor[NMAX];
__device__ int     g_csrc[EMAX + 8 * NMAX];
__device__ int     g_bsum[NBMAX];
__device__ int     g_boff[NBMAX];
__device__ float   g_dis[NMAX];          // (deg+1)^-1/2
__device__ float   g_sdeg[NMAX];         // (deg+1)^+1/2
__device__ float   g_invdeg[NMAX];       // 1/(deg+1)
// row NMAX is the zero pad row: never written, zero-initialized at module load
__device__ __align__(16) __half2 g_uA[(NMAX + 1) * 32];
__device__ __align__(16) __half2 g_uB[(NMAX + 1) * 32];
__device__ __align__(16) __half2 g_hcat2[NMAX * 96];

__device__ __forceinline__ float gelu_exact(float x) {
    return 0.5f * x * (1.0f + erff(x * 0.70710678118654752f));
}

// ---------------- preprocessing ----------------
__global__ void k_hist(const int* __restrict__ ei, int e) {
    int i = blockIdx.x * blockDim.x + threadIdx.x;
    if (i < e) atomicAdd(&g_deg[ei[e + i]], 1);
}

// per-1024-block sums of PADDED degree, fused with aux (dis/sdeg/invdeg)
__global__ void __launch_bounds__(1024) k_blocksum(int n) {
    __shared__ int ws[32];
    int tid = threadIdx.x, lane = tid & 31, wid = tid >> 5;
    int idx = blockIdx.x * 1024 + tid;
    int v = (idx < n) ? g_deg[idx] : 0;
    if (idx < n) {
        float d = (float)(v + 1);
        g_dis[idx] = rsqrtf(d);
        g_sdeg[idx] = sqrtf(d);
        g_invdeg[idx] = 1.0f / d;
    }
    int pv = (idx < n) ? ((v + 7) & ~7) : 0;   // padded degree
    int s = pv;
    #pragma unroll
    for (int o = 16; o; o >>= 1) s += __shfl_xor_sync(0xffffffffu, s, o);
    if (lane == 0) ws[wid] = s;
    __syncthreads();
    if (wid == 0) {
        int u = ws[lane];
        #pragma unroll
        for (int o = 16; o; o >>= 1) u += __shfl_xor_sync(0xffffffffu, u, o);
        if (lane == 0) g_bsum[blockIdx.x] = u;
    }
}

// scans block sums AND writes the padded grand total to g_rowptr[n]
__global__ void k_scanbsums(int nb, int n) {
    int lane = threadIdx.x;
    int carry = 0;
    for (int base = 0; base < nb; base += 32) {
        int idx = base + lane;
        int v = (idx < nb) ? g_bsum[idx] : 0;
        int orig = v;
        #pragma unroll
        for (int o = 1; o < 32; o <<= 1) {
            int t = __shfl_up_sync(0xffffffffu, v, o);
            if (lane >= o) v += t;
        }
        if (idx < nb) g_boff[idx] = carry + v - orig;
        carry += __shfl_sync(0xffffffffu, v, 31);
    }
    if (lane == 0) g_rowptr[n] = carry;   // total padded edge count
}

__global__ void __launch_bounds__(1024) k_scanlocal(int n) {
    __shared__ int wsum[32], woff[32];
    int tid = threadIdx.x, lane = tid & 31, wid = tid >> 5;
    int idx = blockIdx.x * 1024 + tid;
    int pv = (idx < n) ? ((g_deg[idx] + 7) & ~7) : 0;
    int v = pv;
    #pragma unroll
    for (int o = 1; o < 32; o <<= 1) {
        int t = __shfl_up_sync(0xffffffffu, v, o);
        if (lane >= o) v += t;
    }
    if (lane == 31) wsum[wid] = v;
    __syncthreads();
    if (wid == 0) {
        int u = wsum[lane];
        int s = u;
        #pragma unroll
        for (int o = 1; o < 32; o <<= 1) {
            int t = __shfl_up_sync(0xffffffffu, s, o);
            if (lane >= o) s += t;
        }
        woff[lane] = s - u;
    }
    __syncthreads();
    int excl = (v - pv) + woff[wid] + g_boff[blockIdx.x];
    if (idx < n) { g_rowptr[idx] = excl; g_cursor[idx] = excl; }
}

// fill pad slots [rowptr+deg, rowptr+pdeg) with the zero row index n
__global__ void k_fillpad(int n) {
    int i = blockIdx.x * blockDim.x + threadIdx.x;
    if (i < n) {
        int d = g_deg[i];
        int start = g_rowptr[i] + d;
        int stop  = g_rowptr[i] + ((d + 7) & ~7);
        for (int t = start; t < stop; t++) g_csrc[t] = n;
    }
}

__global__ void k_scatter(const int* __restrict__ ei, int e) {
    int i = blockIdx.x * blockDim.x + threadIdx.x;
    if (i < e) {
        int s = ei[i], d = ei[e + i];
        int pos = atomicAdd(&g_cursor[d], 1);
        g_csrc[pos] = s;
    }
}

// ---------------- layer1 GEMM + gelu + LN(64) + dis -> fp16 u0 ----------------
__global__ void __launch_bounds__(256) k_gemm1(const float* __restrict__ x,
                                               const float* __restrict__ W1,
                                               const float* __restrict__ b1,
                                               const float* __restrict__ g1,
                                               const float* __restrict__ be1, int n) {
    __shared__ float xs[64][65];
    __shared__ float ws[64 * 64];
    int tid = threadIdx.x;
    int node0 = blockIdx.x * 64;
    int r = tid >> 2, q = tid & 3;
    float acc[16];
    #pragma unroll
    for (int j = 0; j < 16; j++) acc[j] = 0.f;
    for (int kc = 0; kc < 2; kc++) {
        __syncthreads();
        for (int i = tid; i < 4096; i += 256) ws[i] = W1[kc * 4096 + i];
        for (int i = tid; i < 4096; i += 256) {
            int rr = i >> 6, cc = i & 63;
            int gn = node0 + rr;
            xs[rr][cc] = (gn < n) ? x[gn * IN_F + kc * 64 + cc] : 0.f;
        }
        __syncthreads();
        #pragma unroll 8
        for (int k = 0; k < 64; k++) {
            float xv = xs[r][k];
            const float* wrow = &ws[k * 64];
            #pragma unroll
            for (int j = 0; j < 16; j++) acc[j] = fmaf(xv, wrow[q + 4 * j], acc[j]);
        }
    }
    int gn = node0 + r;
    float s = 0.f, ss = 0.f;
    #pragma unroll
    for (int j = 0; j < 16; j++) {
        int c = q + 4 * j;
        float t = gelu_exact(acc[j] + b1[c]);
        acc[j] = t;
        s += t; ss += t * t;
    }
    s += __shfl_xor_sync(0xffffffffu, s, 1);
    s += __shfl_xor_sync(0xffffffffu, s, 2);
    ss += __shfl_xor_sync(0xffffffffu, ss, 1);
    ss += __shfl_xor_sync(0xffffffffu, ss, 2);
    float mu = s * (1.f / 64.f);
    float var = ss * (1.f / 64.f) - mu * mu;
    float rst = rsqrtf(var + LN_EPS);
    float dis = (gn < n) ? g_dis[gn] : 0.f;
    __syncthreads();
    #pragma unroll
    for (int j = 0; j < 16; j++) {
        int c = q + 4 * j;
        xs[r][c] = ((acc[j] - mu) * rst * g1[c] + be1[c]) * dis;
    }
    __syncthreads();
    for (int i = tid; i < 64 * 32; i += 256) {
        int rr = i >> 5, hc = i & 31;
        int g = node0 + rr;
        if (g < n) g_uA[g * 32 + hc] = __floats2half2_rn(xs[rr][2 * hc], xs[rr][2 * hc + 1]);
    }
}

// ---------------- SpMM hop: 8-lane groups, branch-free padded unroll-8 ----------------
__device__ __forceinline__ void acc_f4(float2 a[4], float4 v) {
    a[0].x += __low2float(*reinterpret_cast<__half2*>(&v.x));
    a[0].y += __high2float(*reinterpret_cast<__half2*>(&v.x));
    a[1].x += __low2float(*reinterpret_cast<__half2*>(&v.y));
    a[1].y += __high2float(*reinterpret_cast<__half2*>(&v.y));
    a[2].x += __low2float(*reinterpret_cast<__half2*>(&v.z));
    a[2].y += __high2float(*reinterpret_cast<__half2*>(&v.z));
    a[3].x += __low2float(*reinterpret_cast<__half2*>(&v.w));
    a[3].y += __high2float(*reinterpret_cast<__half2*>(&v.w));
}

__global__ void __launch_bounds__(256) k_spmm(int dir, int n) {
    int row = (blockIdx.x * blockDim.x + threadIdx.x) >> 3;  // 8-lane group per row
    int gl = threadIdx.x & 7;
    if (row >= n) return;
    const float4* __restrict__ hin = dir ? (const float4*)g_uB : (const float4*)g_uA;
    float4* __restrict__ hout      = dir ? (float4*)g_uA : (float4*)g_uB;
    int beg = __ldg(&g_rowptr[row]), end = __ldg(&g_rowptr[row + 1]);
    int len = end - beg;   // multiple of 8
    const int* __restrict__ cs = g_csrc + beg;
    float2 acc[4] = {{0.f,0.f},{0.f,0.f},{0.f,0.f},{0.f,0.f}};
    // self loop
    acc_f4(acc, __ldg(&hin[row * 8 + gl]));
    for (int k = 0; k < len; k += 8) {
        int s0 = __ldg(cs + k + 0);
        int s1 = __ldg(cs + k + 1);
        int s2 = __ldg(cs + k + 2);
        int s3 = __ldg(cs + k + 3);
        int s4 = __ldg(cs + k + 4);
        int s5 = __ldg(cs + k + 5);
        int s6 = __ldg(cs + k + 6);
        int s7 = __ldg(cs + k + 7);
        float4 v0 = __ldg(&hin[s0 * 8 + gl]);
        float4 v1 = __ldg(&hin[s1 * 8 + gl]);
        float4 v2 = __ldg(&hin[s2 * 8 + gl]);
        float4 v3 = __ldg(&hin[s3 * 8 + gl]);
        float4 v4 = __ldg(&hin[s4 * 8 + gl]);
        float4 v5 = __ldg(&hin[s5 * 8 + gl]);
        float4 v6 = __ldg(&hin[s6 * 8 + gl]);
        float4 v7 = __ldg(&hin[s7 * 8 + gl]);
        acc_f4(acc, v0); acc_f4(acc, v1); acc_f4(acc, v2); acc_f4(acc, v3);
        acc_f4(acc, v4); acc_f4(acc, v5); acc_f4(acc, v6); acc_f4(acc, v7);
    }
    float w = __ldg(&g_invdeg[row]);
    float4 o;
    *reinterpret_cast<__half2*>(&o.x) = __floats2half2_rn(acc[0].x * w, acc[0].y * w);
    *reinterpret_cast<__half2*>(&o.y) = __floats2half2_rn(acc[1].x * w, acc[1].y * w);
    *reinterpret_cast<__half2*>(&o.z) = __floats2half2_rn(acc[2].x * w, acc[2].y * w);
    *reinterpret_cast<__half2*>(&o.w) = __floats2half2_rn(acc[3].x * w, acc[3].y * w);
    hout[row * 8 + gl] = o;
}

// ---------------- per-power GEMM via tensor cores (HMMA m16n8k16) ----------------
// block = 128 threads (4 warps); tile = 64 rows x 64 cols, K = 64
// warp w computes rows [w*16, w*16+16); full N=64 via 8 n-tiles; K in 4 steps of 16
__global__ void __launch_bounds__(128) k_mix_tc(int src, const float* __restrict__ Wc,
                                                const float* __restrict__ bc, int off2, int n) {
    __shared__ __align__(16) __half us[64][72];   // u tile, row-major (rows x K)
    __shared__ __align__(16) __half wsT[64][72];  // W transposed: [c][k]
    __shared__ float bcs[64];
    const __half2* __restrict__ u = src ? g_uB : g_uA;
    int tid = threadIdx.x;
    int node0 = blockIdx.x * 64;
    // load u tile (zero-fill past n)
    for (int i = tid; i < 64 * 32; i += 128) {
        int rr = i >> 5, hc = i & 31;
        int gn = node0 + rr;
        __half2 v = (gn < n) ? u[gn * 32 + hc] : __floats2half2_rn(0.f, 0.f);
        *reinterpret_cast<__half2*>(&us[rr][2 * hc]) = v;
    }
    // load W transposed -> fp16
    for (int i = tid; i < 4096; i += 128) {
        int k = i >> 6, c = i & 63;
        wsT[c][k] = __float2half(Wc[i]);
    }
    if (tid < 64) bcs[tid] = bc[tid];
    __syncthreads();

    int w = tid >> 5, l = tid & 31;
    int qr = l >> 2;            // 0..7
    int qc = (l & 3) * 2;       // 0,2,4,6
    float d[8][4];
    #pragma unroll
    for (int nn = 0; nn < 8; nn++)
        #pragma unroll
        for (int j = 0; j < 4; j++) d[nn][j] = 0.f;

    #pragma unroll
    for (int kk = 0; kk < 4; kk++) {
        int k0 = kk * 16;
        // A fragment (16x16 row-major): regs {r,k},{r+8,k},{r,k+8},{r+8,k+8}
        uint32_t a0 = *reinterpret_cast<const uint32_t*>(&us[w * 16 + qr    ][k0 + qc    ]);
        uint32_t a1 = *reinterpret_cast<const uint32_t*>(&us[w * 16 + qr + 8][k0 + qc    ]);
        uint32_t a2 = *reinterpret_cast<const uint32_t*>(&us[w * 16 + qr    ][k0 + qc + 8]);
        uint32_t a3 = *reinterpret_cast<const uint32_t*>(&us[w * 16 + qr + 8][k0 + qc + 8]);
        #pragma unroll
        for (int nn = 0; nn < 8; nn++) {
            int c = nn * 8 + qr;   // B column this lane supplies
            // B fragment (16x8 col layout): {B[k0+qc][c],B[k0+qc+1][c]}, {B[k0+qc+8][c],B[k0+qc+9][c]}
            uint32_t b0 = *reinterpret_cast<const uint32_t*>(&wsT[c][k0 + qc    ]);
            uint32_t b1 = *reinterpret_cast<const uint32_t*>(&wsT[c][k0 + qc + 8]);
            asm volatile(
                "mma.sync.aligned.m16n8k16.row.col.f32.f16.f16.f32 "
                "{%0,%1,%2,%3}, {%4,%5,%6,%7}, {%8,%9}, {%0,%1,%2,%3};"
                : "+f"(d[nn][0]), "+f"(d[nn][1]), "+f"(d[nn][2]), "+f"(d[nn][3])
                : "r"(a0), "r"(a1), "r"(a2), "r"(a3), "r"(b0), "r"(b1));
        }
    }

    // epilogue: out = d * sdeg[row] + bc[col] -> fp16 hcat
    int r0 = node0 + w * 16 + qr;
    int r1 = r0 + 8;
    float sd0 = (r0 < n) ? g_sdeg[r0] : 0.f;
    float sd1 = (r1 < n) ? g_sdeg[r1] : 0.f;
    #pragma unroll
    for (int nn = 0; nn < 8; nn++) {
        int c = nn * 8 + qc;     // D column pair this lane holds
        float bcl = bcs[c], bch = bcs[c + 1];
        if (r0 < n)
            g_hcat2[r0 * 96 + off2 + (c >> 1)] =
                __floats2half2_rn(d[nn][0] * sd0 + bcl, d[nn][1] * sd0 + bch);
        if (r1 < n)
            g_hcat2[r1 * 96 + off2 + (c >> 1)] =
                __floats2half2_rn(d[nn][2] * sd1 + bcl, d[nn][3] * sd1 + bch);
    }
}

// ---------------- final: gelu + LN(192) + GEMM(192x40) ----------------
__global__ void __launch_bounds__(256) k_final(const float* __restrict__ W2,
                                               const float* __restrict__ b2,
                                               const float* __restrict__ g2,
                                               const float* __restrict__ be2,
                                               float* __restrict__ out, int n) {
    __shared__ float w2s[CAT * OUT_F];
    __shared__ float b2s[OUT_F];
    __shared__ float sv[8][CAT];
    int tid = threadIdx.x;
    for (int i = tid; i < CAT * OUT_F; i += 256) w2s[i] = W2[i];
    if (tid < OUT_F) b2s[tid] = b2[tid];
    __syncthreads();
    int wrp = tid >> 5, lane = tid & 31;
    int node = blockIdx.x * 8 + wrp;
    if (node >= n) return;
    float2 v[3];
    float s = 0.f, ss = 0.f;
    #pragma unroll
    for (int jj = 0; jj < 3; jj++) {
        int p = jj * 32 + lane;
        float2 t = __half22float2(g_hcat2[node * 96 + p]);
        t.x = gelu_exact(t.x);
        t.y = gelu_exact(t.y);
        v[jj] = t;
        s += t.x + t.y;
        ss += t.x * t.x + t.y * t.y;
    }
    #pragma unroll
    for (int o = 16; o; o >>= 1) {
        s  += __shfl_xor_sync(0xffffffffu, s, o);
        ss += __shfl_xor_sync(0xffffffffu, ss, o);
    }
    float mu = s * (1.f / 192.f);
    float var = ss * (1.f / 192.f) - mu * mu;
    float r = rsqrtf(var + LN_EPS);
    #pragma unroll
    for (int jj = 0; jj < 3; jj++) {
        int f0 = 2 * (jj * 32 + lane);
        sv[wrp][f0]     = (v[jj].x - mu) * r * g2[f0]     + be2[f0];
        sv[wrp][f0 + 1] = (v[jj].y - mu) * r * g2[f0 + 1] + be2[f0 + 1];
    }
    __syncwarp();
    for (int c = lane; c < OUT_F; c += 32) {
        float a = b2s[c];
        #pragma unroll 8
        for (int k = 0; k < CAT; k++) a = fmaf(sv[wrp][k], w2s[k * OUT_F + c], a);
        out[node * OUT_F + c] = a;
    }
}

// ---------------- host launcher (serial; R13-fix structure) ----------------
extern "C" void kernel_launch(void* const* d_in, const int* in_sizes, int n_in,
                              void* d_out, int out_size) {
    const float* x  = (const float*)d_in[0];
    const int*   ei = (const int*)d_in[1];
    const float* W1 = (const float*)d_in[2];
    const float* b1 = (const float*)d_in[3];
    const float* Wc = (const float*)d_in[4];
    const float* bc = (const float*)d_in[5];
    const float* W2 = (const float*)d_in[6];
    const float* b2 = (const float*)d_in[7];
    const float* g1 = (const float*)d_in[8];
    const float* be1= (const float*)d_in[9];
    const float* g2 = (const float*)d_in[10];
    const float* be2= (const float*)d_in[11];
    float* out = (float*)d_out;

    int n = in_sizes[0] / IN_F;
    int e = in_sizes[1] / 2;
    int nb = (n + 1023) / 1024;

    void* p = nullptr;
    cudaGetSymbolAddress(&p, g_deg);
    cudaMemsetAsync(p, 0, n * sizeof(int));

    k_hist<<<(e + 255) / 256, 256>>>(ei, e);          // launch 2
    k_blocksum<<<nb, 1024>>>(n);                      // 3
    k_scanbsums<<<1, 32>>>(nb, n);                    // 4
    k_scanlocal<<<nb, 1024>>>(n);                     // 5
    k_gemm1<<<(n + 63) / 64, 256>>>(x, W1, b1, g1, be1, n);  // 6 <- ncu -s 5 target
    k_fillpad<<<(n + 255) / 256, 256>>>(n);           // 7
    k_scatter<<<(e + 255) / 256, 256>>>(ei, e);       // 8

    int sgrid = (n + 31) / 32;
    int wgrid = (n + 7) / 8;
    int mgrid = (n + 63) / 64;
    int dir = 0;
    for (int j = 1; j <= 10; j++) {
        k_spmm<<<sgrid, 256>>>(dir, n);
        int curInB = (dir == 0);
        dir ^= 1;
        if (j == 6)  k_mix_tc<<<mgrid, 128>>>(curInB, Wc + 6 * HID * HID,  bc + 6 * HID,  0,  n);
        if (j == 8)  k_mix_tc<<<mgrid, 128>>>(curInB, Wc + 8 * HID * HID,  bc + 8 * HID,  32, n);
        if (j == 10) k_mix_tc<<<mgrid, 128>>>(curInB, Wc + 10 * HID * HID, bc + 10 * HID, 64, n);
    }

    k_final<<<wgrid, 256>>>(W2, b2, g2, be2, out, n);
}